// round 1
// baseline (speedup 1.0000x reference)
#include <cuda_runtime.h>
#include <math.h>

#define S_LEN 2048
#define BATCH 2
#define NH    16
#define DH    64
#define HID   1024
#define MROWS (BATCH * S_LEN)   // 4096

// -------- scratch (static __device__; no allocations allowed) --------
__device__ float g_Q[MROWS * HID];
__device__ float g_K[MROWS * HID];
__device__ float g_V[MROWS * HID];
__device__ float g_ctx[MROWS * HID];

// ============================================================================
// Generic 64x64-tile fp32 GEMM:  C[m][j] = sum_d A[m][d] * W'(d, j) + bias[j]
//   W'(d, j) for column-tile j0 = 64*blockIdx.x is addressed as
//   Wb = W + blockIdx.x * wTileStride ;  elem(d, jj) = Wb[d * wRowStride + jj]
//   - QKV proj : wTileStride = HID*DH (=65536), wRowStride = DH   (per-head W[h][d][e])
//   - out proj : wTileStride = 64,              wRowStride = HID  (Wo[d][j])
// 256 threads, 4x4 per thread, K-chunk = 32.
// ============================================================================
__global__ __launch_bounds__(256) void gemm64(
    const float* __restrict__ A, const float* __restrict__ W,
    const float* __restrict__ bias, float* __restrict__ C,
    long wTileStride, int wRowStride)
{
    __shared__ float As[64 * 36];   // [m][k], row pitch 36 (4R=144 ≡ 16 mod 32 → no bank conflict)
    __shared__ float Bs[32 * 64];   // [k][e]

    const int j0 = blockIdx.x * 64;
    const int m0 = blockIdx.y * 64;
    const float* Wb = W + (long)blockIdx.x * wTileStride;
    const int tid = threadIdx.x;
    const int tx = tid & 15;
    const int ty = tid >> 4;

    float acc[4][4] = {};

    for (int k0 = 0; k0 < HID; k0 += 32) {
        #pragma unroll
        for (int rr = 0; rr < 2; ++rr) {
            int idx = tid + rr * 256;            // 0..511 float4 slots
            // A tile: 64 rows x 32 k  (8 float4 per row)
            int m  = idx >> 3;
            int kq = (idx & 7) << 2;
            float4 va = *(const float4*)(A + (long)(m0 + m) * HID + k0 + kq);
            *(float4*)&As[m * 36 + kq] = va;
            // B tile: 32 k-rows x 64 cols (16 float4 per row)
            int kk = idx >> 4;
            int eq = (idx & 15) << 2;
            float4 vb = *(const float4*)(Wb + (long)(k0 + kk) * wRowStride + eq);
            *(float4*)&Bs[kk * 64 + eq] = vb;
        }
        __syncthreads();

        #pragma unroll 8
        for (int k = 0; k < 32; ++k) {
            float a0 = As[(ty * 4 + 0) * 36 + k];
            float a1 = As[(ty * 4 + 1) * 36 + k];
            float a2 = As[(ty * 4 + 2) * 36 + k];
            float a3 = As[(ty * 4 + 3) * 36 + k];
            float4 b4 = *(const float4*)&Bs[k * 64 + tx * 4];
            acc[0][0] += a0 * b4.x; acc[0][1] += a0 * b4.y; acc[0][2] += a0 * b4.z; acc[0][3] += a0 * b4.w;
            acc[1][0] += a1 * b4.x; acc[1][1] += a1 * b4.y; acc[1][2] += a1 * b4.z; acc[1][3] += a1 * b4.w;
            acc[2][0] += a2 * b4.x; acc[2][1] += a2 * b4.y; acc[2][2] += a2 * b4.z; acc[2][3] += a2 * b4.w;
            acc[3][0] += a3 * b4.x; acc[3][1] += a3 * b4.y; acc[3][2] += a3 * b4.z; acc[3][3] += a3 * b4.w;
        }
        __syncthreads();
    }

    const float4 bb = *(const float4*)(bias + j0 + tx * 4);
    #pragma unroll
    for (int i = 0; i < 4; ++i) {
        float4 o;
        o.x = acc[i][0] + bb.x;
        o.y = acc[i][1] + bb.y;
        o.z = acc[i][2] + bb.z;
        o.w = acc[i][3] + bb.w;
        *(float4*)(C + (long)(m0 + ty * 4 + i) * HID + j0 + tx * 4) = o;
    }
}

// ============================================================================
// Flash attention, fp32, online softmax.
// grid: (S/64, B*H), 256 threads. Each block: 64 query rows of one (b,h).
// Thread (tx,ty) owns query rows ty*4+i and (score cols / out dims) tx*4+j.
// Shared pitches chosen for conflict-free hot loops:
//   QsT [d][r]  pitch 68 (float4 broadcast)
//   Ks  [c][d]  pitch 65 (scalar over d: row stride ≡ 1 mod 32)
//   Vs  [c][d]  pitch 68 (float4 over d, lanes spread all 32 banks)
//   Ps  [r][c]  pitch 65
// ============================================================================
#define RQ 68
#define RK 65
#define RV 68
#define RP 65
#define FLASH_SMEM_BYTES ((64 * RQ + 64 * RK + 64 * RV + 64 * RP) * 4)  // 68096

__global__ __launch_bounds__(256) void flash_attn()
{
    extern __shared__ float sm[];
    float* QsT = sm;                 // [64 d][RQ]
    float* Ks  = QsT + 64 * RQ;      // [64 c][RK]
    float* Vs  = Ks  + 64 * RK;      // [64 c][RV]
    float* Ps  = Vs  + 64 * RV;      // [64 r][RP]

    const int bh = blockIdx.y;
    const int b  = bh >> 4;
    const int h  = bh & 15;
    const int m0 = blockIdx.x << 6;
    const int tid = threadIdx.x;
    const int tx = tid & 15;
    const int ty = tid >> 4;

    const float* Qg = g_Q + (long)(b * S_LEN) * HID + h * DH;
    const float* Kg = g_K + (long)(b * S_LEN) * HID + h * DH;
    const float* Vg = g_V + (long)(b * S_LEN) * HID + h * DH;

    // Load Q block once, transposed + pre-scaled by 1/sqrt(Dh) = 0.125
    for (int idx = tid; idx < 1024; idx += 256) {
        int rr = idx >> 4;
        int dq = (idx & 15) << 2;
        float4 q = *(const float4*)(Qg + (long)(m0 + rr) * HID + dq);
        QsT[(dq + 0) * RQ + rr] = q.x * 0.125f;
        QsT[(dq + 1) * RQ + rr] = q.y * 0.125f;
        QsT[(dq + 2) * RQ + rr] = q.z * 0.125f;
        QsT[(dq + 3) * RQ + rr] = q.w * 0.125f;
    }

    float acc[4][4] = {};
    float mi[4] = {-1e30f, -1e30f, -1e30f, -1e30f};
    float li[4] = {0.f, 0.f, 0.f, 0.f};

    for (int n0 = 0; n0 < S_LEN; n0 += 64) {
        __syncthreads();   // previous PV done (and Q load on first iter)

        // Load K (scalar scatter, ≤2-way) and V (float4) tiles
        for (int idx = tid; idx < 1024; idx += 256) {
            int c  = idx >> 4;
            int dq = (idx & 15) << 2;
            float4 kv = *(const float4*)(Kg + (long)(n0 + c) * HID + dq);
            Ks[c * RK + dq + 0] = kv.x;
            Ks[c * RK + dq + 1] = kv.y;
            Ks[c * RK + dq + 2] = kv.z;
            Ks[c * RK + dq + 3] = kv.w;
            float4 vv = *(const float4*)(Vg + (long)(n0 + c) * HID + dq);
            *(float4*)&Vs[c * RV + dq] = vv;
        }
        __syncthreads();

        // Scores: s[i][j] = (Q/8)[row_i] . K[col_j]
        float s[4][4] = {};
        #pragma unroll 8
        for (int d = 0; d < 64; ++d) {
            float4 q = *(const float4*)&QsT[d * RQ + ty * 4];
            float k0 = Ks[(tx * 4 + 0) * RK + d];
            float k1 = Ks[(tx * 4 + 1) * RK + d];
            float k2 = Ks[(tx * 4 + 2) * RK + d];
            float k3 = Ks[(tx * 4 + 3) * RK + d];
            s[0][0] += q.x * k0; s[0][1] += q.x * k1; s[0][2] += q.x * k2; s[0][3] += q.x * k3;
            s[1][0] += q.y * k0; s[1][1] += q.y * k1; s[1][2] += q.y * k2; s[1][3] += q.y * k3;
            s[2][0] += q.z * k0; s[2][1] += q.z * k1; s[2][2] += q.z * k2; s[2][3] += q.z * k3;
            s[3][0] += q.w * k0; s[3][1] += q.w * k1; s[3][2] += q.w * k2; s[3][3] += q.w * k3;
        }

        // Online softmax per row (reduce across the 16 tx lanes of a half-warp)
        #pragma unroll
        for (int i = 0; i < 4; ++i) {
            float mx = fmaxf(fmaxf(s[i][0], s[i][1]), fmaxf(s[i][2], s[i][3]));
            #pragma unroll
            for (int o = 1; o < 16; o <<= 1)
                mx = fmaxf(mx, __shfl_xor_sync(0xffffffffu, mx, o));
            float mnew = fmaxf(mi[i], mx);
            float corr = __expf(mi[i] - mnew);   // first tile: exp(-1e30 - finite) = 0
            mi[i] = mnew;
            float rs = 0.f;
            #pragma unroll
            for (int j = 0; j < 4; ++j) {
                s[i][j] = __expf(s[i][j] - mnew);
                rs += s[i][j];
            }
            #pragma unroll
            for (int o = 1; o < 16; o <<= 1)
                rs += __shfl_xor_sync(0xffffffffu, rs, o);
            li[i] = li[i] * corr + rs;
            #pragma unroll
            for (int j = 0; j < 4; ++j)
                acc[i][j] *= corr;
            Ps[(ty * 4 + i) * RP + tx * 4 + 0] = s[i][0];
            Ps[(ty * 4 + i) * RP + tx * 4 + 1] = s[i][1];
            Ps[(ty * 4 + i) * RP + tx * 4 + 2] = s[i][2];
            Ps[(ty * 4 + i) * RP + tx * 4 + 3] = s[i][3];
        }
        __syncthreads();

        // PV: acc[i][j] += sum_c P[row_i][c] * V[c][dim tx*4+j]
        #pragma unroll 8
        for (int c = 0; c < 64; ++c) {
            float4 v = *(const float4*)&Vs[c * RV + tx * 4];
            float p0 = Ps[(ty * 4 + 0) * RP + c];
            float p1 = Ps[(ty * 4 + 1) * RP + c];
            float p2 = Ps[(ty * 4 + 2) * RP + c];
            float p3 = Ps[(ty * 4 + 3) * RP + c];
            acc[0][0] += p0 * v.x; acc[0][1] += p0 * v.y; acc[0][2] += p0 * v.z; acc[0][3] += p0 * v.w;
            acc[1][0] += p1 * v.x; acc[1][1] += p1 * v.y; acc[1][2] += p1 * v.z; acc[1][3] += p1 * v.w;
            acc[2][0] += p2 * v.x; acc[2][1] += p2 * v.y; acc[2][2] += p2 * v.z; acc[2][3] += p2 * v.w;
            acc[3][0] += p3 * v.x; acc[3][1] += p3 * v.y; acc[3][2] += p3 * v.z; acc[3][3] += p3 * v.w;
        }
    }

    // Normalize and write ctx in concat layout [b*S+s][h*64+e]
    #pragma unroll
    for (int i = 0; i < 4; ++i) {
        float inv = 1.0f / li[i];
        float4 o;
        o.x = acc[i][0] * inv;
        o.y = acc[i][1] * inv;
        o.z = acc[i][2] * inv;
        o.w = acc[i][3] * inv;
        *(float4*)(g_ctx + (long)(b * S_LEN + m0 + ty * 4 + i) * HID + h * DH + tx * 4) = o;
    }
}

// ============================================================================
// Launch
// ============================================================================
extern "C" void kernel_launch(void* const* d_in, const int* in_sizes, int n_in,
                              void* d_out, int out_size)
{
    (void)in_sizes; (void)n_in; (void)out_size;
    const float* x  = (const float*)d_in[0];
    const float* Wq = (const float*)d_in[1];
    const float* bq = (const float*)d_in[2];
    const float* Wk = (const float*)d_in[3];
    const float* bk = (const float*)d_in[4];
    const float* Wv = (const float*)d_in[5];
    const float* bv = (const float*)d_in[6];
    const float* Wo = (const float*)d_in[7];
    const float* bo = (const float*)d_in[8];
    float* out = (float*)d_out;

    float *Qp, *Kp, *Vp, *Cp;
    cudaGetSymbolAddress((void**)&Qp, g_Q);
    cudaGetSymbolAddress((void**)&Kp, g_K);
    cudaGetSymbolAddress((void**)&Vp, g_V);
    cudaGetSymbolAddress((void**)&Cp, g_ctx);

    cudaFuncSetAttribute(flash_attn,
                         cudaFuncAttributeMaxDynamicSharedMemorySize,
                         FLASH_SMEM_BYTES);

    dim3 gg(16, 64), tt(256);
    // QKV projections: W'(d, h*64+e) = W[h][d][e]
    gemm64<<<gg, tt>>>(x, Wq, bq, Qp, (long)HID * DH, DH);
    gemm64<<<gg, tt>>>(x, Wk, bk, Kp, (long)HID * DH, DH);
    gemm64<<<gg, tt>>>(x, Wv, bv, Vp, (long)HID * DH, DH);

    flash_attn<<<dim3(S_LEN / 64, BATCH * NH), 256, FLASH_SMEM_BYTES>>>();

    // Output projection: ctx_concat @ Wo + bo
    gemm64<<<gg, tt>>>(Cp, Wo, bo, out, 64L, HID);
}

// round 2
// speedup vs baseline: 3.2771x; 3.2771x over previous
#include <cuda_runtime.h>
#include <math.h>

#define S_LEN 2048
#define BATCH 2
#define NH    16
#define DH    64
#define HID   1024
#define MROWS (BATCH * S_LEN)   // 4096

// -------- scratch (static __device__; no allocations allowed) --------
__device__ float g_Q[MROWS * HID];
__device__ float g_K[MROWS * HID];
__device__ float g_V[MROWS * HID];
__device__ float g_ctx[MROWS * HID];

// ---------------------------------------------------------------------------
// tf32 helpers
// ---------------------------------------------------------------------------
__device__ __forceinline__ unsigned f2tf(float x) {
    unsigned r;
    asm("cvt.rna.tf32.f32 %0, %1;" : "=r"(r) : "f"(x));
    return r;
}

__device__ __forceinline__ void mma8(float* c, const unsigned* a, const unsigned* b) {
    asm volatile(
        "mma.sync.aligned.m16n8k8.row.col.f32.tf32.tf32.f32 "
        "{%0,%1,%2,%3}, {%4,%5,%6,%7}, {%8,%9}, {%0,%1,%2,%3};"
        : "+f"(c[0]), "+f"(c[1]), "+f"(c[2]), "+f"(c[3])
        : "r"(a[0]), "r"(a[1]), "r"(a[2]), "r"(a[3]), "r"(b[0]), "r"(b[1]));
}

// ===========================================================================
// tf32 GEMM:  C[4096 x 1024] = A[4096 x 1024] * W'(d,j) + bias[j]
//   W'(d,j) = W[(j>>6)*wTileStride + d*wRowStride + (j & wColMask)]
//   QKV proj: (65536, 64, 63)   [H][1024][64] per-head weights
//   out proj: (0, 1024, 1023)   [1024][1024] plain
// Block tile 128x128, 8 warps (2m x 4n), warp tile 64x32, k-chunk 32.
// Smem pitches: As[m][36]  (36 ≡ 4 mod 32 -> a-frag reads conflict-free)
//               Bs[k][136] (136 ≡ 8 mod 32 -> b-frag reads conflict-free)
// ===========================================================================
#define AGP 36
#define BGP 136

__global__ __launch_bounds__(256) void gemm_tf32(
    const float* __restrict__ A, const float* __restrict__ W,
    const float* __restrict__ bias, float* __restrict__ C,
    long wTileStride, int wRowStride, int wColMask)
{
    __shared__ unsigned As[128 * AGP];   // [m][k]
    __shared__ unsigned Bs[32 * BGP];    // [k][n]

    const int m0  = blockIdx.y * 128;
    const int j0  = blockIdx.x * 128;
    const int tid = threadIdx.x;
    const int lane = tid & 31;
    const int w    = tid >> 5;
    const int wm = (w >> 2) * 64;   // 2 warps along m
    const int wn = (w & 3) * 32;    // 4 warps along n
    const int lr = lane >> 2;       // 0..7
    const int lc = lane & 3;        // 0..3

    float acc[4][4][4];
    #pragma unroll
    for (int i = 0; i < 4; ++i)
        #pragma unroll
        for (int j = 0; j < 4; ++j)
            #pragma unroll
            for (int k = 0; k < 4; ++k) acc[i][j][k] = 0.f;

    for (int kc = 0; kc < HID; kc += 32) {
        // A tile: 128 m x 32 k, row-major, pitch 36
        #pragma unroll
        for (int i = 0; i < 4; ++i) {
            int linear = tid + i * 256;        // 1024 float4 slots
            int m  = linear >> 3;
            int kq = (linear & 7) << 2;
            float4 v = *(const float4*)(A + (long)(m0 + m) * HID + kc + kq);
            unsigned* d = &As[m * AGP + kq];
            d[0] = f2tf(v.x); d[1] = f2tf(v.y); d[2] = f2tf(v.z); d[3] = f2tf(v.w);
        }
        // B tile: 32 k x 128 n, pitch 136
        #pragma unroll
        for (int i = 0; i < 4; ++i) {
            int linear = tid + i * 256;        // 32k x 32 float4-cols
            int kk = linear >> 5;
            int j  = (linear & 31) << 2;
            int ja = j0 + j;
            const float* p = W + (long)(ja >> 6) * wTileStride
                               + (long)(kc + kk) * wRowStride + (ja & wColMask);
            float4 v = *(const float4*)p;
            unsigned* d = &Bs[kk * BGP + j];
            d[0] = f2tf(v.x); d[1] = f2tf(v.y); d[2] = f2tf(v.z); d[3] = f2tf(v.w);
        }
        __syncthreads();

        #pragma unroll
        for (int ks = 0; ks < 4; ++ks) {
            int kb = ks * 8;
            unsigned a[4][4], b[4][2];
            #pragma unroll
            for (int mt = 0; mt < 4; ++mt) {
                int rm = wm + mt * 16 + lr;
                a[mt][0] = As[rm * AGP + kb + lc];
                a[mt][1] = As[(rm + 8) * AGP + kb + lc];
                a[mt][2] = As[rm * AGP + kb + 4 + lc];
                a[mt][3] = As[(rm + 8) * AGP + kb + 4 + lc];
            }
            #pragma unroll
            for (int nt = 0; nt < 4; ++nt) {
                int cn = wn + nt * 8 + lr;
                b[nt][0] = Bs[(kb + lc) * BGP + cn];
                b[nt][1] = Bs[(kb + 4 + lc) * BGP + cn];
            }
            #pragma unroll
            for (int mt = 0; mt < 4; ++mt)
                #pragma unroll
                for (int nt = 0; nt < 4; ++nt)
                    mma8(acc[mt][nt], a[mt], b[nt]);
        }
        __syncthreads();
    }

    #pragma unroll
    for (int mt = 0; mt < 4; ++mt) {
        int r = m0 + wm + mt * 16 + lr;
        #pragma unroll
        for (int nt = 0; nt < 4; ++nt) {
            int cg = j0 + wn + nt * 8 + lc * 2;
            float b0 = bias[cg], b1 = bias[cg + 1];
            *(float2*)(C + (long)r * HID + cg) =
                make_float2(acc[mt][nt][0] + b0, acc[mt][nt][1] + b1);
            *(float2*)(C + (long)(r + 8) * HID + cg) =
                make_float2(acc[mt][nt][2] + b0, acc[mt][nt][3] + b1);
        }
    }
}

// ===========================================================================
// Flash attention, tf32 tensor-core, online softmax.
// grid (S/64, B*H), 128 threads (4 warps). Warp w owns 16 query rows.
// Q fragments register-resident for the whole kernel (pre-scaled by 1/8).
// Smem (all row-major), pitches chosen for conflict-free fragment reads:
//   Ks[key][68]  (scores B-frag:  bank = 4*lr + lc  -> distinct)
//   Vs[key][72]  (PV     B-frag:  bank = 8*lc + lr  -> distinct)
//   Ps[row][68]  (PV     A-frag:  bank = 4*lr + lc  -> distinct)
// ===========================================================================
#define KP 68
#define VP 72
#define PP 68
#define ATT_SMEM ((64 * KP + 64 * VP + 64 * PP) * 4)   // 53248 bytes

__global__ __launch_bounds__(128) void flash_tf32()
{
    extern __shared__ unsigned smu[];
    unsigned* Ks = smu;                 // [64 key][KP]
    unsigned* Vs = Ks + 64 * KP;        // [64 key][VP]
    unsigned* Ps = Vs + 64 * VP;        // [64 row][PP]

    const int bh = blockIdx.y;
    const int b  = bh >> 4;
    const int h  = bh & 15;
    const int m0 = blockIdx.x << 6;
    const int tid  = threadIdx.x;
    const int lane = tid & 31;
    const int w    = tid >> 5;
    const int lr = lane >> 2;
    const int lc = lane & 3;

    const float* Qg = g_Q + (long)b * S_LEN * HID + h * DH;
    const float* Kg = g_K + (long)b * S_LEN * HID + h * DH;
    const float* Vg = g_V + (long)b * S_LEN * HID + h * DH;

    // Q fragments (m16 x k64 per warp), scaled by 1/sqrt(64)
    unsigned q[8][4];
    {
        const float* Q0 = Qg + (long)(m0 + w * 16 + lr) * HID;
        const float* Q1 = Q0 + 8 * HID;
        #pragma unroll
        for (int ks = 0; ks < 8; ++ks) {
            int kb = ks * 8 + lc;
            q[ks][0] = f2tf(Q0[kb] * 0.125f);
            q[ks][1] = f2tf(Q1[kb] * 0.125f);
            q[ks][2] = f2tf(Q0[kb + 4] * 0.125f);
            q[ks][3] = f2tf(Q1[kb + 4] * 0.125f);
        }
    }

    float o[8][4];
    #pragma unroll
    for (int i = 0; i < 8; ++i)
        #pragma unroll
        for (int j = 0; j < 4; ++j) o[i][j] = 0.f;
    float mi0 = -1e30f, mi1 = -1e30f, li0 = 0.f, li1 = 0.f;

    for (int n0 = 0; n0 < S_LEN; n0 += 64) {
        // Load K/V tiles (64 keys x 64 d), convert to tf32
        #pragma unroll
        for (int i = 0; i < 8; ++i) {
            int linear = tid + i * 128;        // key(64) x 16 float4-cols
            int key = linear >> 4;
            int dq  = (linear & 15) << 2;
            float4 kv = *(const float4*)(Kg + (long)(n0 + key) * HID + dq);
            *(uint4*)&Ks[key * KP + dq] =
                make_uint4(f2tf(kv.x), f2tf(kv.y), f2tf(kv.z), f2tf(kv.w));
            float4 vv = *(const float4*)(Vg + (long)(n0 + key) * HID + dq);
            *(uint4*)&Vs[key * VP + dq] =
                make_uint4(f2tf(vv.x), f2tf(vv.y), f2tf(vv.z), f2tf(vv.w));
        }
        __syncthreads();

        // Scores: S = (Q/8) K^T  -> 8 n-tiles x 8 k-steps of m16n8k8
        float sc[8][4];
        #pragma unroll
        for (int nt = 0; nt < 8; ++nt)
            #pragma unroll
            for (int j = 0; j < 4; ++j) sc[nt][j] = 0.f;
        #pragma unroll
        for (int ks = 0; ks < 8; ++ks) {
            int kb = ks * 8;
            #pragma unroll
            for (int nt = 0; nt < 8; ++nt) {
                unsigned bf[2];
                bf[0] = Ks[(nt * 8 + lr) * KP + kb + lc];
                bf[1] = Ks[(nt * 8 + lr) * KP + kb + 4 + lc];
                mma8(sc[nt], q[ks], bf);
            }
        }

        // Online softmax: thread owns rows lr and lr+8 of the warp's 16
        float mx0 = -1e30f, mx1 = -1e30f;
        #pragma unroll
        for (int nt = 0; nt < 8; ++nt) {
            mx0 = fmaxf(mx0, fmaxf(sc[nt][0], sc[nt][1]));
            mx1 = fmaxf(mx1, fmaxf(sc[nt][2], sc[nt][3]));
        }
        mx0 = fmaxf(mx0, __shfl_xor_sync(0xffffffffu, mx0, 1));
        mx0 = fmaxf(mx0, __shfl_xor_sync(0xffffffffu, mx0, 2));
        mx1 = fmaxf(mx1, __shfl_xor_sync(0xffffffffu, mx1, 1));
        mx1 = fmaxf(mx1, __shfl_xor_sync(0xffffffffu, mx1, 2));

        float mn0 = fmaxf(mi0, mx0), mn1 = fmaxf(mi1, mx1);
        float c0 = __expf(mi0 - mn0), c1 = __expf(mi1 - mn1);
        mi0 = mn0; mi1 = mn1;

        float rs0 = 0.f, rs1 = 0.f;
        #pragma unroll
        for (int nt = 0; nt < 8; ++nt) {
            sc[nt][0] = __expf(sc[nt][0] - mn0); rs0 += sc[nt][0];
            sc[nt][1] = __expf(sc[nt][1] - mn0); rs0 += sc[nt][1];
            sc[nt][2] = __expf(sc[nt][2] - mn1); rs1 += sc[nt][2];
            sc[nt][3] = __expf(sc[nt][3] - mn1); rs1 += sc[nt][3];
        }
        rs0 += __shfl_xor_sync(0xffffffffu, rs0, 1);
        rs0 += __shfl_xor_sync(0xffffffffu, rs0, 2);
        rs1 += __shfl_xor_sync(0xffffffffu, rs1, 1);
        rs1 += __shfl_xor_sync(0xffffffffu, rs1, 2);
        li0 = li0 * c0 + rs0;
        li1 = li1 * c1 + rs1;

        #pragma unroll
        for (int nt = 0; nt < 8; ++nt) {
            o[nt][0] *= c0; o[nt][1] *= c0;
            o[nt][2] *= c1; o[nt][3] *= c1;
        }

        // Stage P (tf32) in smem — warp-private 16 rows
        __syncwarp();
        int pr0 = w * 16 + lr, pr1 = pr0 + 8;
        #pragma unroll
        for (int nt = 0; nt < 8; ++nt) {
            int pc = nt * 8 + lc * 2;
            *(uint2*)&Ps[pr0 * PP + pc] = make_uint2(f2tf(sc[nt][0]), f2tf(sc[nt][1]));
            *(uint2*)&Ps[pr1 * PP + pc] = make_uint2(f2tf(sc[nt][2]), f2tf(sc[nt][3]));
        }
        __syncwarp();

        // PV: O += P V  (k = key dim)
        #pragma unroll
        for (int ks = 0; ks < 8; ++ks) {
            int kb = ks * 8;
            unsigned a[4];
            a[0] = Ps[pr0 * PP + kb + lc];
            a[1] = Ps[pr1 * PP + kb + lc];
            a[2] = Ps[pr0 * PP + kb + 4 + lc];
            a[3] = Ps[pr1 * PP + kb + 4 + lc];
            #pragma unroll
            for (int nt = 0; nt < 8; ++nt) {
                unsigned bf[2];
                bf[0] = Vs[(kb + lc) * VP + nt * 8 + lr];
                bf[1] = Vs[(kb + 4 + lc) * VP + nt * 8 + lr];
                mma8(o[nt], a, bf);
            }
        }
        __syncthreads();
    }

    // Normalize, write ctx in concat layout [b*S+q][h*64+d]
    float inv0 = 1.f / li0, inv1 = 1.f / li1;
    float* Cg = g_ctx + (long)b * S_LEN * HID + h * DH;
    int r0 = m0 + w * 16 + lr;
    #pragma unroll
    for (int nt = 0; nt < 8; ++nt) {
        int cg = nt * 8 + lc * 2;
        *(float2*)(Cg + (long)r0 * HID + cg) =
            make_float2(o[nt][0] * inv0, o[nt][1] * inv0);
        *(float2*)(Cg + (long)(r0 + 8) * HID + cg) =
            make_float2(o[nt][2] * inv1, o[nt][3] * inv1);
    }
}

// ===========================================================================
// Launch
// ===========================================================================
extern "C" void kernel_launch(void* const* d_in, const int* in_sizes, int n_in,
                              void* d_out, int out_size)
{
    (void)in_sizes; (void)n_in; (void)out_size;
    const float* x  = (const float*)d_in[0];
    const float* Wq = (const float*)d_in[1];
    const float* bq = (const float*)d_in[2];
    const float* Wk = (const float*)d_in[3];
    const float* bk = (const float*)d_in[4];
    const float* Wv = (const float*)d_in[5];
    const float* bv = (const float*)d_in[6];
    const float* Wo = (const float*)d_in[7];
    const float* bo = (const float*)d_in[8];
    float* out = (float*)d_out;

    float *Qp, *Kp, *Vp, *Cp;
    cudaGetSymbolAddress((void**)&Qp, g_Q);
    cudaGetSymbolAddress((void**)&Kp, g_K);
    cudaGetSymbolAddress((void**)&Vp, g_V);
    cudaGetSymbolAddress((void**)&Cp, g_ctx);

    cudaFuncSetAttribute(flash_tf32,
                         cudaFuncAttributeMaxDynamicSharedMemorySize, ATT_SMEM);

    dim3 gg(HID / 128, MROWS / 128), tt(256);
    // QKV projections: W'(d, h*64+e) = W[h][d][e]
    gemm_tf32<<<gg, tt>>>(x, Wq, bq, Qp, (long)HID * DH, DH, 63);
    gemm_tf32<<<gg, tt>>>(x, Wk, bk, Kp, (long)HID * DH, DH, 63);
    gemm_tf32<<<gg, tt>>>(x, Wv, bv, Vp, (long)HID * DH, DH, 63);

    flash_tf32<<<dim3(S_LEN / 64, BATCH * NH), 128, ATT_SMEM>>>();

    // Output projection: ctx @ Wo + bo
    gemm_tf32<<<gg, tt>>>(Cp, Wo, bo, out, 0L, HID, 1023);
}